// round 1
// baseline (speedup 1.0000x reference)
#include <cuda_runtime.h>
#include <math.h>

#define BATCH 32
#define TLEN  4096
#define HCH   256
#define NPOS  (BATCH*TLEN)      // 131072
#define LLAYER 4
#define OUTCH 58
#define OPAD  64

// Scratch (device globals: allocation-free rule)
__device__ float g_h[NPOS*HCH];     // 128 MB  (B,T,H) running hidden
__device__ float g_y[NPOS*HCH];     // 128 MB  dwconv+LN+GELU result
__device__ float g_z[NPOS*HCH];     // 128 MB  1x1 GEMM result
__device__ float g_p[NPOS*OPAD];    // 33.5 MB projected spline params (padded to 64)
__device__ float g_pw[OPAD*HCH];    // padded proj weights
__device__ float g_pb[OPAD];
__device__ float g_lad[BATCH*2*TLEN];

__device__ __forceinline__ float block_sum_256(float v){
  __shared__ float sm[8];
  #pragma unroll
  for (int o=16;o;o>>=1) v += __shfl_xor_sync(0xffffffffu, v, o);
  if ((threadIdx.x&31)==0) sm[threadIdx.x>>5]=v;
  __syncthreads();
  float r = sm[0]+sm[1]+sm[2]+sm[3]+sm[4]+sm[5]+sm[6]+sm[7];
  __syncthreads();
  return r;
}

__device__ __forceinline__ float gelu_exact(float x){
  return 0.5f*x*(1.f+erff(x*0.70710678118654752f));
}

__device__ __forceinline__ float softplusf(float x){
  return (x > 20.f) ? x : log1pf(expf(x));
}

// ---------------- pre 1x1: h = pre_w @ x[:, :2] + pre_b ----------------
__global__ void k_pre(const float* __restrict__ x, const float* __restrict__ pw,
                      const float* __restrict__ pb){
  int idx = blockIdx.x*256 + threadIdx.x;      // over NPOS*HCH
  int o = idx & (HCH-1);
  int n = idx >> 8;
  int b = n >> 12, t = n & (TLEN-1);
  float x0 = x[(b*4+0)*TLEN + t];
  float x1 = x[(b*4+1)*TLEN + t];
  float2 w = *(const float2*)&pw[o*2];
  g_h[idx] = fmaf(w.x, x0, fmaf(w.y, x1, pb[o]));
}

// ------- depthwise dilated conv (K=3) + bias + LN(n1) + GELU -> g_y -------
__global__ void k_dwln(const float* __restrict__ mask, const float* __restrict__ sw,
                       const float* __restrict__ sb, const float* __restrict__ gm,
                       const float* __restrict__ bt, int dil){
  int n = blockIdx.x, c = threadIdx.x;
  int t = n & (TLEN-1);
  float w0 = sw[c*3+0], w1 = sw[c*3+1], w2 = sw[c*3+2];
  float v = sb[c] + w1 * g_h[n*HCH+c] * mask[n];
  if (t >= dil)       v += w0 * g_h[(n-dil)*HCH+c] * mask[n-dil];
  if (t + dil < TLEN) v += w2 * g_h[(n+dil)*HCH+c] * mask[n+dil];
  float mean = block_sum_256(v) * (1.f/HCH);
  float d = v - mean;
  float var = block_sum_256(d*d) * (1.f/HCH);
  float yn = d * rsqrtf(var + 1e-5f) * gm[c] + bt[c];
  g_y[n*HCH+c] = gelu_exact(yn);
}

// -------- 256x256 pointwise conv: g_z[n,o] = sum_c W[o,c] g_y[n,c] + b[o] --------
// 128x128 tile, BK=16, 8x8 microtile per thread (256 threads)
__global__ __launch_bounds__(256) void k_gemm256(const float* __restrict__ W,
                                                 const float* __restrict__ bias){
  __shared__ float sA[16][128];
  __shared__ float sB[16][128];
  int tid = threadIdx.x;
  int n0 = blockIdx.x*128;
  int o0 = blockIdx.y*128;
  int tx = tid & 15, ty = tid >> 4;
  float acc[8][8];
  #pragma unroll
  for (int i=0;i<8;i++)
    #pragma unroll
    for (int j=0;j<8;j++) acc[i][j]=0.f;

  for (int c0=0;c0<HCH;c0+=16){
    #pragma unroll
    for (int u=0;u<2;u++){
      int f = tid + u*256;
      int row = f >> 2;
      int cc4 = (f & 3) << 2;
      float4 av = *(const float4*)&g_y[(n0+row)*HCH + c0 + cc4];
      sA[cc4+0][row]=av.x; sA[cc4+1][row]=av.y; sA[cc4+2][row]=av.z; sA[cc4+3][row]=av.w;
      float4 wv = *(const float4*)&W[(o0+row)*HCH + c0 + cc4];
      sB[cc4+0][row]=wv.x; sB[cc4+1][row]=wv.y; sB[cc4+2][row]=wv.z; sB[cc4+3][row]=wv.w;
    }
    __syncthreads();
    #pragma unroll
    for (int cc=0; cc<16; cc++){
      float a[8], b[8];
      *(float4*)&a[0] = *(const float4*)&sA[cc][ty*8];
      *(float4*)&a[4] = *(const float4*)&sA[cc][ty*8+4];
      *(float4*)&b[0] = *(const float4*)&sB[cc][tx*8];
      *(float4*)&b[4] = *(const float4*)&sB[cc][tx*8+4];
      #pragma unroll
      for (int i=0;i<8;i++)
        #pragma unroll
        for (int j=0;j<8;j++) acc[i][j] = fmaf(a[i], b[j], acc[i][j]);
    }
    __syncthreads();
  }
  #pragma unroll
  for (int i=0;i<8;i++){
    int n = n0 + ty*8 + i;
    #pragma unroll
    for (int j=0;j<8;j+=4){
      int o = o0 + tx*8 + j;
      float4 v;
      v.x = acc[i][j+0] + bias[o+0];
      v.y = acc[i][j+1] + bias[o+1];
      v.z = acc[i][j+2] + bias[o+2];
      v.w = acc[i][j+3] + bias[o+3];
      *(float4*)&g_z[n*HCH + o] = v;
    }
  }
}

// -------- LN(n2) + GELU + residual: g_h += gelu(ln(g_z)) --------
__global__ void k_ln2res(const float* __restrict__ gm, const float* __restrict__ bt){
  int n = blockIdx.x, c = threadIdx.x;
  float v = g_z[n*HCH+c];
  float mean = block_sum_256(v) * (1.f/HCH);
  float d = v - mean;
  float var = block_sum_256(d*d) * (1.f/HCH);
  float yn = d * rsqrtf(var + 1e-5f) * gm[c] + bt[c];
  g_h[n*HCH+c] += gelu_exact(yn);
}

// -------- pad proj weights to OPAD=64 rows --------
__global__ void k_padw(const float* __restrict__ pjw, const float* __restrict__ pjb){
  int o = blockIdx.x, c = threadIdx.x;
  g_pw[o*HCH + c] = (o < OUTCH) ? pjw[o*HCH + c] : 0.f;
  if (c == 0) g_pb[o] = (o < OUTCH) ? pjb[o] : 0.f;
}

// -------- projection GEMM 128x64 tile: g_p[n,o] = (W(h*m) + b)*m --------
__global__ __launch_bounds__(256) void k_projgemm(const float* __restrict__ mask){
  __shared__ float sA[16][128];
  __shared__ float sB[16][64];
  int tid = threadIdx.x;
  int n0 = blockIdx.x*128;
  int tx = tid & 7, ty = tid >> 3;     // o = tx*8 (0..63), p = ty*4 (0..124)
  float acc[4][8];
  #pragma unroll
  for (int i=0;i<4;i++)
    #pragma unroll
    for (int j=0;j<8;j++) acc[i][j]=0.f;

  for (int c0=0;c0<HCH;c0+=16){
    #pragma unroll
    for (int u=0;u<2;u++){
      int f = tid + u*256;
      int row = f >> 2;
      int cc4 = (f & 3) << 2;
      float m = mask[n0+row];
      float4 av = *(const float4*)&g_h[(n0+row)*HCH + c0 + cc4];
      sA[cc4+0][row]=av.x*m; sA[cc4+1][row]=av.y*m; sA[cc4+2][row]=av.z*m; sA[cc4+3][row]=av.w*m;
    }
    { // 64x16 weight tile = 256 float4, 1 per thread
      int row = tid >> 2;                  // 0..63
      int cc4 = (tid & 3) << 2;
      float4 wv = *(const float4*)&g_pw[row*HCH + c0 + cc4];
      sB[cc4+0][row]=wv.x; sB[cc4+1][row]=wv.y; sB[cc4+2][row]=wv.z; sB[cc4+3][row]=wv.w;
    }
    __syncthreads();
    #pragma unroll
    for (int cc=0; cc<16; cc++){
      float a[4], b[8];
      *(float4*)&a[0] = *(const float4*)&sA[cc][ty*4];
      *(float4*)&b[0] = *(const float4*)&sB[cc][tx*8];
      *(float4*)&b[4] = *(const float4*)&sB[cc][tx*8+4];
      #pragma unroll
      for (int i=0;i<4;i++)
        #pragma unroll
        for (int j=0;j<8;j++) acc[i][j] = fmaf(a[i], b[j], acc[i][j]);
    }
    __syncthreads();
  }
  #pragma unroll
  for (int i=0;i<4;i++){
    int n = n0 + ty*4 + i;
    float m = mask[n];
    #pragma unroll
    for (int j=0;j<8;j++){
      int o = tx*8 + j;
      g_p[n*OPAD + o] = (acc[i][j] + g_pb[o]) * m;
    }
  }
}

// -------- rational-quadratic spline on x1, write out + per-element lad --------
__global__ void k_spline(const float* __restrict__ x, const float* __restrict__ mask,
                         float* __restrict__ out){
  int i = blockIdx.x*256 + threadIdx.x;      // over BATCH*2*TLEN
  int t = i & (TLEN-1);
  int bc = i >> 12;
  int c = bc & 1, b = bc >> 1;
  float m = mask[b*TLEN + t];
  const float* p = &g_p[(b*TLEN + t)*OPAD + c*29];
  float x1 = x[(b*4 + 2 + c)*TLEN + t];

  // copy-through channel (x0 * mask)
  out[(b*4 + c)*TLEN + t] = x[(b*4 + c)*TLEN + t] * m;

  const float scale = 0.0625f;   // 1/sqrt(256)
  float ew[10], eh[10];
  float mw = -1e30f, mh = -1e30f;
  #pragma unroll
  for (int j=0;j<10;j++){ mw = fmaxf(mw, p[j]*scale); mh = fmaxf(mh, p[10+j]*scale); }
  float sw = 0.f, sh = 0.f;
  #pragma unroll
  for (int j=0;j<10;j++){
    ew[j] = expf(p[j]*scale - mw);    sw += ew[j];
    eh[j] = expf(p[10+j]*scale - mh); sh += eh[j];
  }
  float invsw = 1.f/sw, invsh = 1.f/sh;
  float xc = fminf(fmaxf(x1, -5.f), 5.f);

  float cumw = 0.f, cumh = 0.f;
  float cwj = -5.f, chj = -5.f;
  int idx = 9;
  float in_cw = 0.f, in_w = 1.f, in_ch = 0.f, in_h = 1.f;
  bool found = false;
  #pragma unroll
  for (int j=0;j<10;j++){
    cumw += 0.001f + 0.99f*ew[j]*invsw;
    cumh += 0.001f + 0.99f*eh[j]*invsh;
    float nw = (j==9) ? 5.f : fmaf(10.f, cumw, -5.f);
    float nh = (j==9) ? 5.f : fmaf(10.f, cumh, -5.f);
    if (!found && (xc < nw || j==9)){
      found = true; idx = j;
      in_cw = cwj; in_w = nw - cwj;
      in_ch = chj; in_h = nh - chj;
    }
    cwj = nw; chj = nh;
  }
  float dk  = (idx==0) ? 1.f : 0.001f + softplusf(p[20 + idx - 1]);
  float dk1 = (idx==9) ? 1.f : 0.001f + softplusf(p[20 + idx]);
  float delta = in_h / in_w;
  float th  = (xc - in_cw) / in_w;
  float th2 = th*th;
  float t1m = th*(1.f - th);
  float num = in_h * (delta*th2 + dk*t1m);
  float den = delta + (dk + dk1 - 2.f*delta)*t1m;
  float y = in_ch + num/den;
  float omt = 1.f - th;
  float dnum = delta*delta*(dk1*th2 + 2.f*delta*t1m + dk*omt*omt);
  float lad = logf(dnum) - 2.f*logf(den);

  bool inside = (x1 >= -5.f) && (x1 <= 5.f);
  y   = inside ? y   : x1;
  lad = inside ? lad : 0.f;

  out[(b*4 + 2 + c)*TLEN + t] = y * m;
  g_lad[i] = lad * m;
}

// -------- deterministic logdet reduction per batch --------
__global__ void k_reduce(float* __restrict__ out){
  int b = blockIdx.x;
  float s = 0.f;
  for (int j = threadIdx.x; j < 2*TLEN; j += 256) s += g_lad[b*2*TLEN + j];
  s = block_sum_256(s);
  if (threadIdx.x == 0) out[BATCH*4*TLEN + b] = s;
}

extern "C" void kernel_launch(void* const* d_in, const int* in_sizes, int n_in,
                              void* d_out, int out_size){
  const float* x     = (const float*)d_in[0];
  const float* xm    = (const float*)d_in[1];
  const float* pre_w = (const float*)d_in[2];
  const float* pre_b = (const float*)d_in[3];
  const float* sep_w = (const float*)d_in[4];
  const float* sep_b = (const float*)d_in[5];
  const float* c1w   = (const float*)d_in[6];
  const float* c1b   = (const float*)d_in[7];
  const float* n1g   = (const float*)d_in[8];
  const float* n1b   = (const float*)d_in[9];
  const float* n2g   = (const float*)d_in[10];
  const float* n2b   = (const float*)d_in[11];
  const float* pjw   = (const float*)d_in[12];
  const float* pjb   = (const float*)d_in[13];
  float* out = (float*)d_out;

  k_pre<<<(NPOS*HCH)/256, 256>>>(x, pre_w, pre_b);

  int dil = 1;
  for (int i=0;i<LLAYER;i++){
    k_dwln<<<NPOS, 256>>>(xm, sep_w + i*HCH*3, sep_b + i*HCH,
                          n1g + i*HCH, n1b + i*HCH, dil);
    dim3 gg(NPOS/128, HCH/128);
    k_gemm256<<<gg, 256>>>(c1w + i*HCH*HCH, c1b + i*HCH);
    k_ln2res<<<NPOS, 256>>>(n2g + i*HCH, n2b + i*HCH);
    dil *= 3;
  }

  k_padw<<<OPAD, HCH>>>(pjw, pjb);
  k_projgemm<<<NPOS/128, 256>>>(xm);
  k_spline<<<(BATCH*2*TLEN)/256, 256>>>(x, xm, out);
  k_reduce<<<BATCH, 256>>>(out);
}

// round 3
// speedup vs baseline: 1.5810x; 1.5810x over previous
#include <cuda_runtime.h>
#include <cuda_bf16.h>
#include <math.h>
#include <stdint.h>

#define BATCH 32
#define TLEN  4096
#define HCH   256
#define NPOS  (BATCH*TLEN)      // 131072
#define LLAYER 4
#define OUTCH 58
#define OPAD  64

// ---------------- scratch (device globals; allocation-free rule) ----------------
__device__ float          g_h [NPOS*HCH];          // fp32 running hidden (B*T, H)
__device__ __nv_bfloat16  g_yh[NPOS*HCH];          // bf16 hi of dwln output
__device__ __nv_bfloat16  g_yl[NPOS*HCH];          // bf16 lo
__device__ __nv_bfloat16  g_wh[LLAYER*HCH*HCH];    // bf16 hi of 1x1 weights
__device__ __nv_bfloat16  g_wl[LLAYER*HCH*HCH];
__device__ float g_p[NPOS*OPAD];
__device__ float g_pw[OPAD*HCH];
__device__ float g_pb[OPAD];
__device__ float g_lad[BATCH*2*TLEN];

// ---------------- helpers ----------------
__device__ __forceinline__ uint32_t smem_u32(const void* p){
  uint32_t a;
  asm("{ .reg .u64 t; cvta.to.shared.u64 t, %1; cvt.u32.u64 %0, t; }" : "=r"(a) : "l"(p));
  return a;
}
__device__ __forceinline__ unsigned lds32(uint32_t a){
  unsigned v; asm volatile("ld.shared.b32 %0, [%1];" : "=r"(v) : "r"(a)); return v;
}
__device__ __forceinline__ void cp16(uint32_t d, const void* s){
  asm volatile("cp.async.cg.shared.global [%0], [%1], 16;" :: "r"(d), "l"(s));
}
#define CP_COMMIT() asm volatile("cp.async.commit_group;")

__device__ __forceinline__ void mma16816(float* d, const unsigned* a, unsigned b0, unsigned b1){
  asm volatile("mma.sync.aligned.m16n8k16.row.col.f32.bf16.bf16.f32 "
    "{%0,%1,%2,%3}, {%4,%5,%6,%7}, {%8,%9}, {%0,%1,%2,%3};"
    : "+f"(d[0]),"+f"(d[1]),"+f"(d[2]),"+f"(d[3])
    : "r"(a[0]),"r"(a[1]),"r"(a[2]),"r"(a[3]),"r"(b0),"r"(b1));
}

__device__ __forceinline__ float gelu_exact(float x){
  return 0.5f*x*(1.f+erff(x*0.70710678118654752f));
}
__device__ __forceinline__ float softplusf(float x){
  return (x > 20.f) ? x : log1pf(expf(x));
}

// ---------------- pre 1x1 ----------------
__global__ void k_pre(const float* __restrict__ x, const float* __restrict__ pw,
                      const float* __restrict__ pb){
  int idx = blockIdx.x*256 + threadIdx.x;
  int o = idx & (HCH-1);
  int n = idx >> 8;
  int b = n >> 12, t = n & (TLEN-1);
  float x0 = x[(b*4+0)*TLEN + t];
  float x1 = x[(b*4+1)*TLEN + t];
  float2 w = *(const float2*)&pw[o*2];
  g_h[idx] = fmaf(w.x, x0, fmaf(w.y, x1, pb[o]));
}

// ---------------- split weights to bf16 hi/lo ----------------
__global__ void k_wprep(const float* __restrict__ w){
  int i = blockIdx.x*256 + threadIdx.x;
  float v = w[i];
  __nv_bfloat16 h = __float2bfloat16(v);
  g_wh[i] = h;
  g_wl[i] = __float2bfloat16(v - __bfloat162float(h));
}

// ------- depthwise dilated conv + bias + LN(n1) + GELU -> bf16 hi/lo -------
__global__ void k_dwln(const float* __restrict__ mask, const float* __restrict__ sw,
                       const float* __restrict__ sb, const float* __restrict__ gm,
                       const float* __restrict__ bt, int dil){
  int w = threadIdx.x >> 5, lid = threadIdx.x & 31;
  int n = blockIdx.x*8 + w;
  int t = n & (TLEN-1);
  int c = lid*8;

  float m0 = mask[n];
  float hc[8], v[8];
  *(float4*)&hc[0] = *(const float4*)&g_h[n*HCH + c];
  *(float4*)&hc[4] = *(const float4*)&g_h[n*HCH + c + 4];
  #pragma unroll
  for (int j=0;j<8;j++) v[j] = sb[c+j] + sw[(c+j)*3+1]*hc[j]*m0;

  if (t >= dil){
    float mm = mask[n-dil];
    float hl[8];
    *(float4*)&hl[0] = *(const float4*)&g_h[(n-dil)*HCH + c];
    *(float4*)&hl[4] = *(const float4*)&g_h[(n-dil)*HCH + c + 4];
    #pragma unroll
    for (int j=0;j<8;j++) v[j] += sw[(c+j)*3+0]*hl[j]*mm;
  }
  if (t + dil < TLEN){
    float mm = mask[n+dil];
    float hr[8];
    *(float4*)&hr[0] = *(const float4*)&g_h[(n+dil)*HCH + c];
    *(float4*)&hr[4] = *(const float4*)&g_h[(n+dil)*HCH + c + 4];
    #pragma unroll
    for (int j=0;j<8;j++) v[j] += sw[(c+j)*3+2]*hr[j]*mm;
  }

  float ls = 0.f;
  #pragma unroll
  for (int j=0;j<8;j++) ls += v[j];
  #pragma unroll
  for (int o=16;o;o>>=1) ls += __shfl_xor_sync(0xffffffffu, ls, o);
  float mean = ls * (1.f/HCH);
  float sq = 0.f;
  #pragma unroll
  for (int j=0;j<8;j++){ v[j] -= mean; sq += v[j]*v[j]; }
  #pragma unroll
  for (int o=16;o;o>>=1) sq += __shfl_xor_sync(0xffffffffu, sq, o);
  float rstd = rsqrtf(sq * (1.f/HCH) + 1e-5f);

  __nv_bfloat16 hi[8], lo[8];
  #pragma unroll
  for (int j=0;j<8;j++){
    float yn = v[j]*rstd*gm[c+j] + bt[c+j];
    float ge = gelu_exact(yn);
    __nv_bfloat16 h = __float2bfloat16(ge);
    hi[j] = h;
    lo[j] = __float2bfloat16(ge - __bfloat162float(h));
  }
  *(uint4*)&g_yh[n*HCH + c] = *(uint4*)&hi[0];
  *(uint4*)&g_yl[n*HCH + c] = *(uint4*)&lo[0];
}

// ======== fused mma.sync GEMM: z = W y + b ; g_h += gelu(LN(z)) ========
// CTA: 64 positions x 256 out-ch. 8 warps (2M x 4N), warp tile 32x64.
// K = 256 per phase, 3 phases (yh*wh, yh*wl, yl*wh), chunked KC=32.
#define A_STRIDE 80
#define A_BUF    5120            // 64 rows * 80B
#define B_STRIDE 80
#define B_BUF    20480           // 256 rows * 80B
#define OFF_A    0
#define OFF_B    10240
#define OFF_PAR  51200           // 3 * 1024B (bias, g, bt)
#define OFF_RED  54272           // 64 rows * 8 floats
#define GSMEM    56320

__global__ void __launch_bounds__(256, 2) k_gemmfused(int layer,
                       const float* __restrict__ bias,
                       const float* __restrict__ gm, const float* __restrict__ bt){
  extern __shared__ char smem[];
  uint32_t sbase = smem_u32(smem);
  float* s_bias = (float*)(smem + OFF_PAR);
  float* s_g    = (float*)(smem + OFF_PAR + 1024);
  float* s_bt   = (float*)(smem + OFF_PAR + 2048);
  float* s_red  = (float*)(smem + OFF_RED);

  int tid = threadIdx.x, lane = tid & 31, wid = tid >> 5;
  int warpM = wid >> 2, warpN = wid & 3;
  int g = lane >> 2, tig = lane & 3;
  int n0 = blockIdx.x * 64;

  const __nv_bfloat16* wh = &g_wh[layer*HCH*HCH];
  const __nv_bfloat16* wl = &g_wl[layer*HCH*HCH];

  s_bias[tid] = bias[tid]; s_g[tid] = gm[tid]; s_bt[tid] = bt[tid];

  float acc[2][8][4];
  #pragma unroll
  for (int mf=0;mf<2;mf++)
    #pragma unroll
    for (int nf=0;nf<8;nf++)
      #pragma unroll
      for (int k=0;k<4;k++) acc[mf][nf][k]=0.f;

  // per-thread global load coords
  int arow = tid >> 2;            // 0..63
  int acol = (tid & 3) * 8;       // bf16 elems
  uint32_t sa_st = sbase + OFF_A + arow*A_STRIDE + (tid&3)*16;
  uint32_t sb_st = sbase + OFF_B + arow*B_STRIDE + (tid&3)*16;

  #define ISSUE(q) {                                                        \
    int _q = (q);                                                           \
    const __nv_bfloat16* srcA = (_q < 16) ? g_yh : g_yl;                    \
    const __nv_bfloat16* srcB = (_q >= 8 && _q < 16) ? wl : wh;             \
    int kc = (_q & 7) * 32;                                                 \
    int bo = (_q & 1) ? 1 : 0;                                              \
    cp16(sa_st + bo*A_BUF, srcA + (size_t)(n0 + arow)*HCH + kc + acol);     \
    cp16(sb_st + bo*B_BUF +   0*64*B_STRIDE, srcB + (size_t)(arow+  0)*HCH + kc + acol); \
    cp16(sb_st + bo*B_BUF +   1*64*B_STRIDE, srcB + (size_t)(arow+ 64)*HCH + kc + acol); \
    cp16(sb_st + bo*B_BUF +   2*64*B_STRIDE, srcB + (size_t)(arow+128)*HCH + kc + acol); \
    cp16(sb_st + bo*B_BUF +   3*64*B_STRIDE, srcB + (size_t)(arow+192)*HCH + kc + acol); \
    CP_COMMIT();                                                            \
  }

  ISSUE(0);

  for (int q = 0; q < 24; q++){
    if (q + 1 < 24) ISSUE(q+1);
    if (q + 1 < 24) asm volatile("cp.async.wait_group 1;");
    else            asm volatile("cp.async.wait_group 0;");
    __syncthreads();

    int buf = q & 1;
    uint32_t aBase = sbase + OFF_A + buf*A_BUF + (warpM*32)*A_STRIDE;
    uint32_t bBase = sbase + OFF_B + buf*B_BUF + (warpN*64)*B_STRIDE;

    #pragma unroll
    for (int ks=0; ks<2; ks++){
      int kb = ks*32;   // 16 elems * 2B
      unsigned afr[2][4];
      #pragma unroll
      for (int mf=0; mf<2; mf++){
        uint32_t r0 = aBase + (mf*16 + g)*A_STRIDE + kb + tig*4;
        afr[mf][0] = lds32(r0);
        afr[mf][1] = lds32(r0 + 8*A_STRIDE);
        afr[mf][2] = lds32(r0 + 16);
        afr[mf][3] = lds32(r0 + 8*A_STRIDE + 16);
      }
      #pragma unroll
      for (int nf=0; nf<8; nf++){
        uint32_t rb = bBase + (nf*8 + g)*B_STRIDE + kb + tig*4;
        unsigned b0 = lds32(rb);
        unsigned b1 = lds32(rb + 16);
        mma16816(acc[0][nf], afr[0], b0, b1);
        mma16816(acc[1][nf], afr[1], b0, b1);
      }
    }
    __syncthreads();
  }

  // ---- epilogue: bias, row stats, LN, GELU, residual ----
  float s[4]  = {0.f,0.f,0.f,0.f};
  float sq[4] = {0.f,0.f,0.f,0.f};
  #pragma unroll
  for (int mf=0; mf<2; mf++)
    #pragma unroll
    for (int nf=0; nf<8; nf++){
      int ch0 = warpN*64 + nf*8 + tig*2;
      float b0 = s_bias[ch0], b1 = s_bias[ch0+1];
      acc[mf][nf][0]+=b0; acc[mf][nf][1]+=b1;
      acc[mf][nf][2]+=b0; acc[mf][nf][3]+=b1;
      s [mf*2+0] += acc[mf][nf][0]+acc[mf][nf][1];
      sq[mf*2+0] += acc[mf][nf][0]*acc[mf][nf][0] + acc[mf][nf][1]*acc[mf][nf][1];
      s [mf*2+1] += acc[mf][nf][2]+acc[mf][nf][3];
      sq[mf*2+1] += acc[mf][nf][2]*acc[mf][nf][2] + acc[mf][nf][3]*acc[mf][nf][3];
    }
  #pragma unroll
  for (int sl=0; sl<4; sl++){
    s [sl] += __shfl_xor_sync(0xffffffffu, s [sl], 1);
    s [sl] += __shfl_xor_sync(0xffffffffu, s [sl], 2);
    sq[sl] += __shfl_xor_sync(0xffffffffu, sq[sl], 1);
    sq[sl] += __shfl_xor_sync(0xffffffffu, sq[sl], 2);
  }
  if (tig == 0){
    #pragma unroll
    for (int sl=0; sl<4; sl++){
      int mf = sl >> 1, h = sl & 1;
      int row = warpM*32 + mf*16 + h*8 + g;
      s_red[row*8 + warpN*2 + 0] = s[sl];
      s_red[row*8 + warpN*2 + 1] = sq[sl];
    }
  }
  __syncthreads();

  float mean_[4], rstd_[4];
  #pragma unroll
  for (int sl=0; sl<4; sl++){
    int mf = sl >> 1, h = sl & 1;
    int row = warpM*32 + mf*16 + h*8 + g;
    float su = s_red[row*8+0]+s_red[row*8+2]+s_red[row*8+4]+s_red[row*8+6];
    float qq = s_red[row*8+1]+s_red[row*8+3]+s_red[row*8+5]+s_red[row*8+7];
    float mn = su * (1.f/HCH);
    float var = qq * (1.f/HCH) - mn*mn;
    mean_[sl] = mn;
    rstd_[sl] = rsqrtf(var + 1e-5f);
  }

  #pragma unroll
  for (int mf=0; mf<2; mf++)
    #pragma unroll
    for (int nf=0; nf<8; nf++){
      int ch0 = warpN*64 + nf*8 + tig*2;
      float g0 = s_g[ch0], g1 = s_g[ch0+1];
      float t0 = s_bt[ch0], t1 = s_bt[ch0+1];
      #pragma unroll
      for (int h=0; h<2; h++){
        int sl = mf*2 + h;
        int row = n0 + warpM*32 + mf*16 + h*8 + g;
        float v0 = (acc[mf][nf][h*2+0] - mean_[sl])*rstd_[sl]*g0 + t0;
        float v1 = (acc[mf][nf][h*2+1] - mean_[sl])*rstd_[sl]*g1 + t1;
        float2* ptr = (float2*)&g_h[(size_t)row*HCH + ch0];
        float2 hv = *ptr;
        hv.x += gelu_exact(v0);
        hv.y += gelu_exact(v1);
        *ptr = hv;
      }
    }
}

// ---------------- pad proj weights ----------------
__global__ void k_padw(const float* __restrict__ pjw, const float* __restrict__ pjb){
  int o = blockIdx.x, c = threadIdx.x;
  g_pw[o*HCH + c] = (o < OUTCH) ? pjw[o*HCH + c] : 0.f;
  if (c == 0) g_pb[o] = (o < OUTCH) ? pjb[o] : 0.f;
}

// ---------------- projection GEMM (SIMT fp32) ----------------
__global__ void __launch_bounds__(256) k_projgemm(const float* __restrict__ mask){
  __shared__ float sA[16][128];
  __shared__ float sB[16][64];
  int tid = threadIdx.x;
  int n0 = blockIdx.x*128;
  int tx = tid & 7, ty = tid >> 3;
  float acc[4][8];
  #pragma unroll
  for (int i=0;i<4;i++)
    #pragma unroll
    for (int j=0;j<8;j++) acc[i][j]=0.f;

  for (int c0=0;c0<HCH;c0+=16){
    #pragma unroll
    for (int u=0;u<2;u++){
      int f = tid + u*256;
      int row = f >> 2;
      int cc4 = (f & 3) << 2;
      float m = mask[n0+row];
      float4 av = *(const float4*)&g_h[(size_t)(n0+row)*HCH + c0 + cc4];
      sA[cc4+0][row]=av.x*m; sA[cc4+1][row]=av.y*m; sA[cc4+2][row]=av.z*m; sA[cc4+3][row]=av.w*m;
    }
    {
      int row = tid >> 2;
      int cc4 = (tid & 3) << 2;
      float4 wv = *(const float4*)&g_pw[row*HCH + c0 + cc4];
      sB[cc4+0][row]=wv.x; sB[cc4+1][row]=wv.y; sB[cc4+2][row]=wv.z; sB[cc4+3][row]=wv.w;
    }
    __syncthreads();
    #pragma unroll
    for (int cc=0; cc<16; cc++){
      float a[4], b[8];
      *(float4*)&a[0] = *(const float4*)&sA[cc][ty*4];
      *(float4*)&b[0] = *(const float4*)&sB[cc][tx*8];
      *(float4*)&b[4] = *(const float4*)&sB[cc][tx*8+4];
      #pragma unroll
      for (int i=0;i<4;i++)
        #pragma unroll
        for (int j=0;j<8;j++) acc[i][j] = fmaf(a[i], b[j], acc[i][j]);
    }
    __syncthreads();
  }
  #pragma unroll
  for (int i=0;i<4;i++){
    int n = n0 + ty*4 + i;
    float m = mask[n];
    #pragma unroll
    for (int j=0;j<8;j++){
      int o = tx*8 + j;
      g_p[n*OPAD + o] = (acc[i][j] + g_pb[o]) * m;
    }
  }
}

// ---------------- rational-quadratic spline ----------------
__global__ void k_spline(const float* __restrict__ x, const float* __restrict__ mask,
                         float* __restrict__ out){
  int i = blockIdx.x*256 + threadIdx.x;
  int t = i & (TLEN-1);
  int bc = i >> 12;
  int c = bc & 1, b = bc >> 1;
  float m = mask[b*TLEN + t];
  const float* p = &g_p[(size_t)(b*TLEN + t)*OPAD + c*29];
  float x1 = x[(b*4 + 2 + c)*TLEN + t];

  out[(b*4 + c)*TLEN + t] = x[(b*4 + c)*TLEN + t] * m;

  const float scale = 0.0625f;
  float ew[10], eh[10];
  float mw = -1e30f, mh = -1e30f;
  #pragma unroll
  for (int j=0;j<10;j++){ mw = fmaxf(mw, p[j]*scale); mh = fmaxf(mh, p[10+j]*scale); }
  float sw = 0.f, sh = 0.f;
  #pragma unroll
  for (int j=0;j<10;j++){
    ew[j] = expf(p[j]*scale - mw);    sw += ew[j];
    eh[j] = expf(p[10+j]*scale - mh); sh += eh[j];
  }
  float invsw = 1.f/sw, invsh = 1.f/sh;
  float xc = fminf(fmaxf(x1, -5.f), 5.f);

  float cumw = 0.f, cumh = 0.f;
  float cwj = -5.f, chj = -5.f;
  int idx = 9;
  float in_cw = 0.f, in_w = 1.f, in_ch = 0.f, in_h = 1.f;
  bool found = false;
  #pragma unroll
  for (int j=0;j<10;j++){
    cumw += 0.001f + 0.99f*ew[j]*invsw;
    cumh += 0.001f + 0.99f*eh[j]*invsh;
    float nw = (j==9) ? 5.f : fmaf(10.f, cumw, -5.f);
    float nh = (j==9) ? 5.f : fmaf(10.f, cumh, -5.f);
    if (!found && (xc < nw || j==9)){
      found = true; idx = j;
      in_cw = cwj; in_w = nw - cwj;
      in_ch = chj; in_h = nh - chj;
    }
    cwj = nw; chj = nh;
  }
  float dk  = (idx==0) ? 1.f : 0.001f + softplusf(p[20 + idx - 1]);
  float dk1 = (idx==9) ? 1.f : 0.001f + softplusf(p[20 + idx]);
  float delta = in_h / in_w;
  float th  = (xc - in_cw) / in_w;
  float th2 = th*th;
  float t1m = th*(1.f - th);
  float num = in_h * (delta*th2 + dk*t1m);
  float den = delta + (dk + dk1 - 2.f*delta)*t1m;
  float y = in_ch + num/den;
  float omt = 1.f - th;
  float dnum = delta*delta*(dk1*th2 + 2.f*delta*t1m + dk*omt*omt);
  float lad = logf(dnum) - 2.f*logf(den);

  bool inside = (x1 >= -5.f) && (x1 <= 5.f);
  y   = inside ? y   : x1;
  lad = inside ? lad : 0.f;

  out[(b*4 + 2 + c)*TLEN + t] = y * m;
  g_lad[i] = lad * m;
}

__global__ void k_reduce(float* __restrict__ out){
  int b = blockIdx.x;
  float s = 0.f;
  for (int j = threadIdx.x; j < 2*TLEN; j += 256) s += g_lad[b*2*TLEN + j];
  __shared__ float sm[8];
  #pragma unroll
  for (int o=16;o;o>>=1) s += __shfl_xor_sync(0xffffffffu, s, o);
  if ((threadIdx.x&31)==0) sm[threadIdx.x>>5]=s;
  __syncthreads();
  if (threadIdx.x == 0){
    float r = sm[0]+sm[1]+sm[2]+sm[3]+sm[4]+sm[5]+sm[6]+sm[7];
    out[BATCH*4*TLEN + b] = r;
  }
}

extern "C" void kernel_launch(void* const* d_in, const int* in_sizes, int n_in,
                              void* d_out, int out_size){
  const float* x     = (const float*)d_in[0];
  const float* xm    = (const float*)d_in[1];
  const float* pre_w = (const float*)d_in[2];
  const float* pre_b = (const float*)d_in[3];
  const float* sep_w = (const float*)d_in[4];
  const float* sep_b = (const float*)d_in[5];
  const float* c1w   = (const float*)d_in[6];
  const float* c1b   = (const float*)d_in[7];
  const float* n1g   = (const float*)d_in[8];
  const float* n1b   = (const float*)d_in[9];
  const float* n2g   = (const float*)d_in[10];
  const float* n2b   = (const float*)d_in[11];
  const float* pjw   = (const float*)d_in[12];
  const float* pjb   = (const float*)d_in[13];
  float* out = (float*)d_out;

  static int smem_set = 0;
  if (!smem_set){
    cudaFuncSetAttribute(k_gemmfused, cudaFuncAttributeMaxDynamicSharedMemorySize, GSMEM);
    smem_set = 1;
  }

  k_pre<<<(NPOS*HCH)/256, 256>>>(x, pre_w, pre_b);
  k_wprep<<<(LLAYER*HCH*HCH)/256, 256>>>(c1w);

  int dil = 1;
  for (int i=0;i<LLAYER;i++){
    k_dwln<<<NPOS/8, 256>>>(xm, sep_w + i*HCH*3, sep_b + i*HCH,
                            n1g + i*HCH, n1b + i*HCH, dil);
    k_gemmfused<<<NPOS/64, 256, GSMEM>>>(i, c1b + i*HCH, n2g + i*HCH, n2b + i*HCH);
    dil *= 3;
  }

  k_padw<<<OPAD, HCH>>>(pjw, pjb);
  k_projgemm<<<NPOS/128, 256>>>(xm);
  k_spline<<<(BATCH*2*TLEN)/256, 256>>>(x, xm, out);
  k_reduce<<<BATCH, 256>>>(out);
}

// round 4
// speedup vs baseline: 1.8149x; 1.1479x over previous
#include <cuda_runtime.h>
#include <cuda_bf16.h>
#include <math.h>
#include <stdint.h>

#define BATCH 32
#define TLEN  4096
#define HCH   256
#define NPOS  (BATCH*TLEN)      // 131072
#define LLAYER 4
#define OUTCH 58
#define OPAD  64

// ---------------- scratch (device globals; allocation-free rule) ----------------
__device__ float g_h [NPOS*HCH];          // fp32 running hidden (B*T, H)
__device__ float g_y [NPOS*HCH];          // tf32-rounded dwln output
__device__ float g_wt[LLAYER*HCH*HCH];    // tf32-rounded 1x1 weights
__device__ float g_p[NPOS*OPAD];
__device__ float g_pw[OPAD*HCH];
__device__ float g_pb[OPAD];
__device__ float g_lad[BATCH*2*TLEN];

// ---------------- helpers ----------------
__device__ __forceinline__ uint32_t smem_u32(const void* p){
  uint32_t a;
  asm("{ .reg .u64 t; cvta.to.shared.u64 t, %1; cvt.u32.u64 %0, t; }" : "=r"(a) : "l"(p));
  return a;
}
__device__ __forceinline__ unsigned lds32(uint32_t a){
  unsigned v; asm volatile("ld.shared.b32 %0, [%1];" : "=r"(v) : "r"(a)); return v;
}
__device__ __forceinline__ void cp16(uint32_t d, const void* s){
  asm volatile("cp.async.cg.shared.global [%0], [%1], 16;" :: "r"(d), "l"(s));
}
#define CP_COMMIT() asm volatile("cp.async.commit_group;")

__device__ __forceinline__ void mma_tf32(float* d, const unsigned* a, unsigned b0, unsigned b1){
  asm volatile("mma.sync.aligned.m16n8k8.row.col.f32.tf32.tf32.f32 "
    "{%0,%1,%2,%3}, {%4,%5,%6,%7}, {%8,%9}, {%0,%1,%2,%3};"
    : "+f"(d[0]),"+f"(d[1]),"+f"(d[2]),"+f"(d[3])
    : "r"(a[0]),"r"(a[1]),"r"(a[2]),"r"(a[3]),"r"(b0),"r"(b1));
}
__device__ __forceinline__ float tf32_rna(float x){
  uint32_t r;
  asm("cvt.rna.tf32.f32 %0, %1;" : "=r"(r) : "f"(x));
  return __uint_as_float(r);
}
__device__ __forceinline__ float gelu_exact(float x){
  return 0.5f*x*(1.f+erff(x*0.70710678118654752f));
}
__device__ __forceinline__ float softplusf(float x){
  return (x > 20.f) ? x : log1pf(expf(x));
}

// ---------------- pre 1x1 ----------------
__global__ void k_pre(const float* __restrict__ x, const float* __restrict__ pw,
                      const float* __restrict__ pb){
  int idx = blockIdx.x*256 + threadIdx.x;
  int o = idx & (HCH-1);
  int n = idx >> 8;
  int b = n >> 12, t = n & (TLEN-1);
  float x0 = x[(b*4+0)*TLEN + t];
  float x1 = x[(b*4+1)*TLEN + t];
  float2 w = *(const float2*)&pw[o*2];
  g_h[idx] = fmaf(w.x, x0, fmaf(w.y, x1, pb[o]));
}

// ---------------- round weights to tf32 ----------------
__global__ void k_wprep(const float* __restrict__ w){
  int i = blockIdx.x*256 + threadIdx.x;
  g_wt[i] = tf32_rna(w[i]);
}

// ------- depthwise dilated conv + bias + LN(n1) + GELU -> tf32-rounded fp32 -------
__global__ void k_dwln(const float* __restrict__ mask, const float* __restrict__ sw,
                       const float* __restrict__ sb, const float* __restrict__ gm,
                       const float* __restrict__ bt, int dil){
  int w = threadIdx.x >> 5, lid = threadIdx.x & 31;
  int n = blockIdx.x*8 + w;
  int t = n & (TLEN-1);
  int c = lid*8;

  float m0 = mask[n];
  float hc[8], v[8];
  *(float4*)&hc[0] = *(const float4*)&g_h[(size_t)n*HCH + c];
  *(float4*)&hc[4] = *(const float4*)&g_h[(size_t)n*HCH + c + 4];
  #pragma unroll
  for (int j=0;j<8;j++) v[j] = sb[c+j] + sw[(c+j)*3+1]*hc[j]*m0;

  if (t >= dil){
    float mm = mask[n-dil];
    float hl[8];
    *(float4*)&hl[0] = *(const float4*)&g_h[(size_t)(n-dil)*HCH + c];
    *(float4*)&hl[4] = *(const float4*)&g_h[(size_t)(n-dil)*HCH + c + 4];
    #pragma unroll
    for (int j=0;j<8;j++) v[j] += sw[(c+j)*3+0]*hl[j]*mm;
  }
  if (t + dil < TLEN){
    float mm = mask[n+dil];
    float hr[8];
    *(float4*)&hr[0] = *(const float4*)&g_h[(size_t)(n+dil)*HCH + c];
    *(float4*)&hr[4] = *(const float4*)&g_h[(size_t)(n+dil)*HCH + c + 4];
    #pragma unroll
    for (int j=0;j<8;j++) v[j] += sw[(c+j)*3+2]*hr[j]*mm;
  }

  float ls = 0.f;
  #pragma unroll
  for (int j=0;j<8;j++) ls += v[j];
  #pragma unroll
  for (int o=16;o;o>>=1) ls += __shfl_xor_sync(0xffffffffu, ls, o);
  float mean = ls * (1.f/HCH);
  float sq = 0.f;
  #pragma unroll
  for (int j=0;j<8;j++){ v[j] -= mean; sq += v[j]*v[j]; }
  #pragma unroll
  for (int o=16;o;o>>=1) sq += __shfl_xor_sync(0xffffffffu, sq, o);
  float rstd = rsqrtf(sq * (1.f/HCH) + 1e-5f);

  float o_[8];
  #pragma unroll
  for (int j=0;j<8;j++){
    float yn = v[j]*rstd*gm[c+j] + bt[c+j];
    o_[j] = tf32_rna(gelu_exact(yn));
  }
  *(float4*)&g_y[(size_t)n*HCH + c]     = *(float4*)&o_[0];
  *(float4*)&g_y[(size_t)n*HCH + c + 4] = *(float4*)&o_[4];
}

// ======== fused tf32 mma GEMM: z = W y + b ; g_h += gelu(LN(z)) ========
// CTA: 64 positions x 256 out-ch. 8 warps (2M x 4N), warp tile 32x64.
// Single phase tf32, K=256, chunk KC=32 floats (128B), 8 chunks, double buffer.
#define RSTR   144               // row stride bytes (128 data + 16 pad)
#define A_BUF  9216              // 64 * 144
#define B_BUF  36864             // 256 * 144
#define OFF_A  0
#define OFF_B  (2*A_BUF)                  // 18432
#define OFF_PAR (OFF_B + 2*B_BUF)         // 92160
#define OFF_RED (OFF_PAR + 3072)          // 95232
#define GSMEM   (OFF_RED + 2048)          // 97280

__global__ void __launch_bounds__(256, 2) k_gemmfused(int layer,
                       const float* __restrict__ bias,
                       const float* __restrict__ gm, const float* __restrict__ bt){
  extern __shared__ char smem[];
  uint32_t sbase = smem_u32(smem);
  float* s_bias = (float*)(smem + OFF_PAR);
  float* s_g    = (float*)(smem + OFF_PAR + 1024);
  float* s_bt   = (float*)(smem + OFF_PAR + 2048);
  float* s_red  = (float*)(smem + OFF_RED);

  int tid = threadIdx.x, lane = tid & 31, wid = tid >> 5;
  int warpM = wid >> 2, warpN = wid & 3;
  int g = lane >> 2, tig = lane & 3;
  int n0 = blockIdx.x * 64;

  const char* wt = (const char*)(g_wt + (size_t)layer*HCH*HCH);
  const char* ya = (const char*)g_y;

  s_bias[tid] = bias[tid]; s_g[tid] = gm[tid]; s_bt[tid] = bt[tid];

  float acc[2][8][4];
  #pragma unroll
  for (int mf=0;mf<2;mf++)
    #pragma unroll
    for (int nf=0;nf<8;nf++)
      #pragma unroll
      for (int k=0;k<4;k++) acc[mf][nf][k]=0.f;

  int arow = tid >> 2;            // 0..63
  int aq   = (tid & 3) * 32;      // byte offset within 128B segment
  uint32_t sa_st = sbase + OFF_A + arow*RSTR + aq;
  uint32_t sb_st = sbase + OFF_B + arow*RSTR + aq;
  const char* gA = ya + (size_t)(n0 + arow)*1024 + aq;

  #define ISSUE(q) {                                                       \
    int _kc = (q)*128;                                                     \
    int _bo = ((q)&1);                                                     \
    cp16(sa_st + _bo*A_BUF,      gA + _kc);                                \
    cp16(sa_st + _bo*A_BUF + 16, gA + _kc + 16);                           \
    _Pragma("unroll")                                                      \
    for (int _j=0;_j<4;_j++){                                              \
      const char* _s = wt + (size_t)(arow + 64*_j)*1024 + _kc + aq;        \
      uint32_t _d = sb_st + _bo*B_BUF + (64*_j)*RSTR;                      \
      cp16(_d, _s); cp16(_d + 16, _s + 16);                                \
    }                                                                      \
    CP_COMMIT();                                                           \
  }

  ISSUE(0);

  for (int q = 0; q < 8; q++){
    if (q + 1 < 8){ ISSUE(q+1); asm volatile("cp.async.wait_group 1;"); }
    else          {             asm volatile("cp.async.wait_group 0;"); }
    __syncthreads();

    int buf = q & 1;
    uint32_t aBase = sbase + OFF_A + buf*A_BUF + (warpM*32)*RSTR;
    uint32_t bBase = sbase + OFF_B + buf*B_BUF + (warpN*64)*RSTR;

    #pragma unroll
    for (int ks=0; ks<4; ks++){
      int kb = ks*32;           // 8 floats per k-step
      unsigned afr[2][4];
      #pragma unroll
      for (int mf=0; mf<2; mf++){
        uint32_t r0 = aBase + (mf*16 + g)*RSTR + kb + tig*4;
        afr[mf][0] = lds32(r0);
        afr[mf][1] = lds32(r0 + 8*RSTR);
        afr[mf][2] = lds32(r0 + 16);
        afr[mf][3] = lds32(r0 + 8*RSTR + 16);
      }
      #pragma unroll
      for (int nf=0; nf<8; nf++){
        uint32_t rb = bBase + (nf*8 + g)*RSTR + kb + tig*4;
        unsigned b0 = lds32(rb);
        unsigned b1 = lds32(rb + 16);
        mma_tf32(acc[0][nf], afr[0], b0, b1);
        mma_tf32(acc[1][nf], afr[1], b0, b1);
      }
    }
    __syncthreads();
  }

  // ---- epilogue: bias, row stats, LN, GELU, residual ----
  float s[4]  = {0.f,0.f,0.f,0.f};
  float sq[4] = {0.f,0.f,0.f,0.f};
  #pragma unroll
  for (int mf=0; mf<2; mf++)
    #pragma unroll
    for (int nf=0; nf<8; nf++){
      int ch0 = warpN*64 + nf*8 + tig*2;
      float b0 = s_bias[ch0], b1 = s_bias[ch0+1];
      acc[mf][nf][0]+=b0; acc[mf][nf][1]+=b1;
      acc[mf][nf][2]+=b0; acc[mf][nf][3]+=b1;
      s [mf*2+0] += acc[mf][nf][0]+acc[mf][nf][1];
      sq[mf*2+0] += acc[mf][nf][0]*acc[mf][nf][0] + acc[mf][nf][1]*acc[mf][nf][1];
      s [mf*2+1] += acc[mf][nf][2]+acc[mf][nf][3];
      sq[mf*2+1] += acc[mf][nf][2]*acc[mf][nf][2] + acc[mf][nf][3]*acc[mf][nf][3];
    }
  #pragma unroll
  for (int sl=0; sl<4; sl++){
    s [sl] += __shfl_xor_sync(0xffffffffu, s [sl], 1);
    s [sl] += __shfl_xor_sync(0xffffffffu, s [sl], 2);
    sq[sl] += __shfl_xor_sync(0xffffffffu, sq[sl], 1);
    sq[sl] += __shfl_xor_sync(0xffffffffu, sq[sl], 2);
  }
  if (tig == 0){
    #pragma unroll
    for (int sl=0; sl<4; sl++){
      int mf = sl >> 1, h = sl & 1;
      int row = warpM*32 + mf*16 + h*8 + g;
      s_red[row*8 + warpN*2 + 0] = s[sl];
      s_red[row*8 + warpN*2 + 1] = sq[sl];
    }
  }
  __syncthreads();

  float mean_[4], rstd_[4];
  #pragma unroll
  for (int sl=0; sl<4; sl++){
    int mf = sl >> 1, h = sl & 1;
    int row = warpM*32 + mf*16 + h*8 + g;
    float su = s_red[row*8+0]+s_red[row*8+2]+s_red[row*8+4]+s_red[row*8+6];
    float qq = s_red[row*8+1]+s_red[row*8+3]+s_red[row*8+5]+s_red[row*8+7];
    float mn = su * (1.f/HCH);
    float var = qq * (1.f/HCH) - mn*mn;
    mean_[sl] = mn;
    rstd_[sl] = rsqrtf(var + 1e-5f);
  }

  #pragma unroll
  for (int mf=0; mf<2; mf++)
    #pragma unroll
    for (int nf=0; nf<8; nf++){
      int ch0 = warpN*64 + nf*8 + tig*2;
      float g0 = s_g[ch0], g1 = s_g[ch0+1];
      float t0 = s_bt[ch0], t1 = s_bt[ch0+1];
      #pragma unroll
      for (int h=0; h<2; h++){
        int sl = mf*2 + h;
        int row = n0 + warpM*32 + mf*16 + h*8 + g;
        float v0 = (acc[mf][nf][h*2+0] - mean_[sl])*rstd_[sl]*g0 + t0;
        float v1 = (acc[mf][nf][h*2+1] - mean_[sl])*rstd_[sl]*g1 + t1;
        float2* ptr = (float2*)&g_h[(size_t)row*HCH + ch0];
        float2 hv = *ptr;
        hv.x += gelu_exact(v0);
        hv.y += gelu_exact(v1);
        *ptr = hv;
      }
    }
}

// ---------------- pad proj weights ----------------
__global__ void k_padw(const float* __restrict__ pjw, const float* __restrict__ pjb){
  int o = blockIdx.x, c = threadIdx.x;
  g_pw[o*HCH + c] = (o < OUTCH) ? pjw[o*HCH + c] : 0.f;
  if (c == 0) g_pb[o] = (o < OUTCH) ? pjb[o] : 0.f;
}

// ---------------- projection GEMM (SIMT fp32) ----------------
__global__ void __launch_bounds__(256) k_projgemm(const float* __restrict__ mask){
  __shared__ float sA[16][128];
  __shared__ float sB[16][64];
  int tid = threadIdx.x;
  int n0 = blockIdx.x*128;
  int tx = tid & 7, ty = tid >> 3;
  float acc[4][8];
  #pragma unroll
  for (int i=0;i<4;i++)
    #pragma unroll
    for (int j=0;j<8;j++) acc[i][j]=0.f;

  for (int c0=0;c0<HCH;c0+=16){
    #pragma unroll
    for (int u=0;u<2;u++){
      int f = tid + u*256;
      int row = f >> 2;
      int cc4 = (f & 3) << 2;
      float m = mask[n0+row];
      float4 av = *(const float4*)&g_h[(size_t)(n0+row)*HCH + c0 + cc4];
      sA[cc4+0][row]=av.x*m; sA[cc4+1][row]=av.y*m; sA[cc4+2][row]=av.z*m; sA[cc4+3][row]=av.w*m;
    }
    {
      int row = tid >> 2;
      int cc4 = (tid & 3) << 2;
      float4 wv = *(const float4*)&g_pw[row*HCH + c0 + cc4];
      sB[cc4+0][row]=wv.x; sB[cc4+1][row]=wv.y; sB[cc4+2][row]=wv.z; sB[cc4+3][row]=wv.w;
    }
    __syncthreads();
    #pragma unroll
    for (int cc=0; cc<16; cc++){
      float a[4], b[8];
      *(float4*)&a[0] = *(const float4*)&sA[cc][ty*4];
      *(float4*)&b[0] = *(const float4*)&sB[cc][tx*8];
      *(float4*)&b[4] = *(const float4*)&sB[cc][tx*8+4];
      #pragma unroll
      for (int i=0;i<4;i++)
        #pragma unroll
        for (int j=0;j<8;j++) acc[i][j] = fmaf(a[i], b[j], acc[i][j]);
    }
    __syncthreads();
  }
  #pragma unroll
  for (int i=0;i<4;i++){
    int n = n0 + ty*4 + i;
    float m = mask[n];
    #pragma unroll
    for (int j=0;j<8;j++){
      int o = tx*8 + j;
      g_p[n*OPAD + o] = (acc[i][j] + g_pb[o]) * m;
    }
  }
}

// ---------------- rational-quadratic spline ----------------
__global__ void k_spline(const float* __restrict__ x, const float* __restrict__ mask,
                         float* __restrict__ out){
  int i = blockIdx.x*256 + threadIdx.x;
  int t = i & (TLEN-1);
  int bc = i >> 12;
  int c = bc & 1, b = bc >> 1;
  float m = mask[b*TLEN + t];
  const float* p = &g_p[(size_t)(b*TLEN + t)*OPAD + c*29];
  float x1 = x[(b*4 + 2 + c)*TLEN + t];

  out[(b*4 + c)*TLEN + t] = x[(b*4 + c)*TLEN + t] * m;

  const float scale = 0.0625f;
  float ew[10], eh[10];
  float mw = -1e30f, mh = -1e30f;
  #pragma unroll
  for (int j=0;j<10;j++){ mw = fmaxf(mw, p[j]*scale); mh = fmaxf(mh, p[10+j]*scale); }
  float sw = 0.f, sh = 0.f;
  #pragma unroll
  for (int j=0;j<10;j++){
    ew[j] = expf(p[j]*scale - mw);    sw += ew[j];
    eh[j] = expf(p[10+j]*scale - mh); sh += eh[j];
  }
  float invsw = 1.f/sw, invsh = 1.f/sh;
  float xc = fminf(fmaxf(x1, -5.f), 5.f);

  float cumw = 0.f, cumh = 0.f;
  float cwj = -5.f, chj = -5.f;
  int idx = 9;
  float in_cw = 0.f, in_w = 1.f, in_ch = 0.f, in_h = 1.f;
  bool found = false;
  #pragma unroll
  for (int j=0;j<10;j++){
    cumw += 0.001f + 0.99f*ew[j]*invsw;
    cumh += 0.001f + 0.99f*eh[j]*invsh;
    float nw = (j==9) ? 5.f : fmaf(10.f, cumw, -5.f);
    float nh = (j==9) ? 5.f : fmaf(10.f, cumh, -5.f);
    if (!found && (xc < nw || j==9)){
      found = true; idx = j;
      in_cw = cwj; in_w = nw - cwj;
      in_ch = chj; in_h = nh - chj;
    }
    cwj = nw; chj = nh;
  }
  float dk  = (idx==0) ? 1.f : 0.001f + softplusf(p[20 + idx - 1]);
  float dk1 = (idx==9) ? 1.f : 0.001f + softplusf(p[20 + idx]);
  float delta = in_h / in_w;
  float th  = (xc - in_cw) / in_w;
  float th2 = th*th;
  float t1m = th*(1.f - th);
  float num = in_h * (delta*th2 + dk*t1m);
  float den = delta + (dk + dk1 - 2.f*delta)*t1m;
  float y = in_ch + num/den;
  float omt = 1.f - th;
  float dnum = delta*delta*(dk1*th2 + 2.f*delta*t1m + dk*omt*omt);
  float lad = logf(dnum) - 2.f*logf(den);

  bool inside = (x1 >= -5.f) && (x1 <= 5.f);
  y   = inside ? y   : x1;
  lad = inside ? lad : 0.f;

  out[(b*4 + 2 + c)*TLEN + t] = y * m;
  g_lad[i] = lad * m;
}

__global__ void k_reduce(float* __restrict__ out){
  int b = blockIdx.x;
  float s = 0.f;
  for (int j = threadIdx.x; j < 2*TLEN; j += 256) s += g_lad[b*2*TLEN + j];
  __shared__ float sm[8];
  #pragma unroll
  for (int o=16;o;o>>=1) s += __shfl_xor_sync(0xffffffffu, s, o);
  if ((threadIdx.x&31)==0) sm[threadIdx.x>>5]=s;
  __syncthreads();
  if (threadIdx.x == 0){
    float r = sm[0]+sm[1]+sm[2]+sm[3]+sm[4]+sm[5]+sm[6]+sm[7];
    out[BATCH*4*TLEN + b] = r;
  }
}

extern "C" void kernel_launch(void* const* d_in, const int* in_sizes, int n_in,
                              void* d_out, int out_size){
  const float* x     = (const float*)d_in[0];
  const float* xm    = (const float*)d_in[1];
  const float* pre_w = (const float*)d_in[2];
  const float* pre_b = (const float*)d_in[3];
  const float* sep_w = (const float*)d_in[4];
  const float* sep_b = (const float*)d_in[5];
  const float* c1w   = (const float*)d_in[6];
  const float* c1b   = (const float*)d_in[7];
  const float* n1g   = (const float*)d_in[8];
  const float* n1b   = (const float*)d_in[9];
  const float* n2g   = (const float*)d_in[10];
  const float* n2b   = (const float*)d_in[11];
  const float* pjw   = (const float*)d_in[12];
  const float* pjb   = (const float*)d_in[13];
  float* out = (float*)d_out;

  static int smem_set = 0;
  if (!smem_set){
    cudaFuncSetAttribute(k_gemmfused, cudaFuncAttributeMaxDynamicSharedMemorySize, GSMEM);
    smem_set = 1;
  }

  k_pre<<<(NPOS*HCH)/256, 256>>>(x, pre_w, pre_b);
  k_wprep<<<(LLAYER*HCH*HCH)/256, 256>>>(c1w);

  int dil = 1;
  for (int i=0;i<LLAYER;i++){
    k_dwln<<<NPOS/8, 256>>>(xm, sep_w + i*HCH*3, sep_b + i*HCH,
                            n1g + i*HCH, n1b + i*HCH, dil);
    k_gemmfused<<<NPOS/64, 256, GSMEM>>>(i, c1b + i*HCH, n2g + i*HCH, n2b + i*HCH);
    dil *= 3;
  }

  k_padw<<<OPAD, HCH>>>(pjw, pjb);
  k_projgemm<<<NPOS/128, 256>>>(xm);
  k_spline<<<(BATCH*2*TLEN)/256, 256>>>(x, xm, out);
  k_reduce<<<BATCH, 256>>>(out);
}

// round 6
// speedup vs baseline: 1.8510x; 1.0199x over previous
#include <cuda_runtime.h>
#include <cuda_bf16.h>
#include <math.h>
#include <stdint.h>

#define BATCH 32
#define TLEN  4096
#define HCH   256
#define NPOS  (BATCH*TLEN)      // 131072
#define LLAYER 4
#define OUTCH 58
#define OPAD  64

// ---------------- scratch (device globals; allocation-free rule) ----------------
__device__ float g_h [NPOS*HCH];          // fp32 running hidden (B*T, H)
__device__ float g_y [NPOS*HCH];          // tf32-rounded dwln output
__device__ float g_wt[LLAYER*HCH*HCH];    // tf32-rounded 1x1 weights
__device__ float g_p[NPOS*OPAD];
__device__ float g_pw[OPAD*HCH];
__device__ float g_pb[OPAD];
__device__ float g_lad[BATCH*2*TLEN];

// ---------------- helpers ----------------
__device__ __forceinline__ uint32_t smem_u32(const void* p){
  uint32_t a;
  asm("{ .reg .u64 t; cvta.to.shared.u64 t, %1; cvt.u32.u64 %0, t; }" : "=r"(a) : "l"(p));
  return a;
}
__device__ __forceinline__ void cp16(uint32_t d, const void* s){
  asm volatile("cp.async.cg.shared.global [%0], [%1], 16;" :: "r"(d), "l"(s));
}
#define CP_COMMIT() asm volatile("cp.async.commit_group;")

__device__ __forceinline__ void ldsm4(unsigned &r0, unsigned &r1, unsigned &r2, unsigned &r3, uint32_t a){
  asm volatile("ldmatrix.sync.aligned.m8n8.x4.shared.b16 {%0,%1,%2,%3}, [%4];"
    : "=r"(r0),"=r"(r1),"=r"(r2),"=r"(r3) : "r"(a));
}
__device__ __forceinline__ void mma_tf32(float* d, const unsigned* a, unsigned b0, unsigned b1){
  asm volatile("mma.sync.aligned.m16n8k8.row.col.f32.tf32.tf32.f32 "
    "{%0,%1,%2,%3}, {%4,%5,%6,%7}, {%8,%9}, {%0,%1,%2,%3};"
    : "+f"(d[0]),"+f"(d[1]),"+f"(d[2]),"+f"(d[3])
    : "r"(a[0]),"r"(a[1]),"r"(a[2]),"r"(a[3]),"r"(b0),"r"(b1));
}
__device__ __forceinline__ float tf32_rna(float x){
  uint32_t r;
  asm("cvt.rna.tf32.f32 %0, %1;" : "=r"(r) : "f"(x));
  return __uint_as_float(r);
}
__device__ __forceinline__ float gelu_exact(float x){
  return 0.5f*x*(1.f+erff(x*0.70710678118654752f));
}
__device__ __forceinline__ float softplusf(float x){
  return (x > 20.f) ? x : log1pf(expf(x));
}

// ---------------- pre 1x1 ----------------
__global__ void k_pre(const float* __restrict__ x, const float* __restrict__ pw,
                      const float* __restrict__ pb){
  int idx = blockIdx.x*256 + threadIdx.x;
  int o = idx & (HCH-1);
  int n = idx >> 8;
  int b = n >> 12, t = n & (TLEN-1);
  float x0 = x[(b*4+0)*TLEN + t];
  float x1 = x[(b*4+1)*TLEN + t];
  float2 w = *(const float2*)&pw[o*2];
  g_h[idx] = fmaf(w.x, x0, fmaf(w.y, x1, pb[o]));
}

// ---------------- round weights to tf32 ----------------
__global__ void k_wprep(const float* __restrict__ w){
  int i = blockIdx.x*256 + threadIdx.x;
  g_wt[i] = tf32_rna(w[i]);
}

// ------- depthwise dilated conv + bias + LN(n1) + GELU -> tf32-rounded fp32 -------
__global__ void k_dwln(const float* __restrict__ mask, const float* __restrict__ sw,
                       const float* __restrict__ sb, const float* __restrict__ gm,
                       const float* __restrict__ bt, int dil){
  int w = threadIdx.x >> 5, lid = threadIdx.x & 31;
  int n = blockIdx.x*8 + w;
  int t = n & (TLEN-1);
  int c = lid*8;

  float m0 = mask[n];
  float hc[8], v[8];
  *(float4*)&hc[0] = *(const float4*)&g_h[(size_t)n*HCH + c];
  *(float4*)&hc[4] = *(const float4*)&g_h[(size_t)n*HCH + c + 4];
  #pragma unroll
  for (int j=0;j<8;j++) v[j] = sb[c+j] + sw[(c+j)*3+1]*hc[j]*m0;

  if (t >= dil){
    float mm = mask[n-dil];
    float hl[8];
    *(float4*)&hl[0] = *(const float4*)&g_h[(size_t)(n-dil)*HCH + c];
    *(float4*)&hl[4] = *(const float4*)&g_h[(size_t)(n-dil)*HCH + c + 4];
    #pragma unroll
    for (int j=0;j<8;j++) v[j] += sw[(c+j)*3+0]*hl[j]*mm;
  }
  if (t + dil < TLEN){
    float mm = mask[n+dil];
    float hr[8];
    *(float4*)&hr[0] = *(const float4*)&g_h[(size_t)(n+dil)*HCH + c];
    *(float4*)&hr[4] = *(const float4*)&g_h[(size_t)(n+dil)*HCH + c + 4];
    #pragma unroll
    for (int j=0;j<8;j++) v[j] += sw[(c+j)*3+2]*hr[j]*mm;
  }

  float ls = 0.f;
  #pragma unroll
  for (int j=0;j<8;j++) ls += v[j];
  #pragma unroll
  for (int o=16;o;o>>=1) ls += __shfl_xor_sync(0xffffffffu, ls, o);
  float mean = ls * (1.f/HCH);
  float sq = 0.f;
  #pragma unroll
  for (int j=0;j<8;j++){ v[j] -= mean; sq += v[j]*v[j]; }
  #pragma unroll
  for (int o=16;o;o>>=1) sq += __shfl_xor_sync(0xffffffffu, sq, o);
  float rstd = rsqrtf(sq * (1.f/HCH) + 1e-5f);

  float o_[8];
  #pragma unroll
  for (int j=0;j<8;j++){
    float yn = v[j]*rstd*gm[c+j] + bt[c+j];
    o_[j] = tf32_rna(gelu_exact(yn));
  }
  *(float4*)&g_y[(size_t)n*HCH + c]     = *(float4*)&o_[0];
  *(float4*)&g_y[(size_t)n*HCH + c + 4] = *(float4*)&o_[4];
}

// ======== fused tf32 mma GEMM: z = W y + b ; g_h += gelu(LN(z)) ========
// CTA: 64 positions x 256 out-ch. 8 warps (2M x 4N), warp tile 32x64.
// K=256, chunk KC=32 floats (128B), 8 chunks, double buffer, ldmatrix fragments.
#define RSTR   144               // row stride bytes (128 data + 16 pad)
#define A_BUF  9216              // 64 * 144
#define B_BUF  36864             // 256 * 144
#define OFF_A  0
#define OFF_B  (2*A_BUF)                  // 18432
#define OFF_PAR (OFF_B + 2*B_BUF)         // 92160
#define OFF_RED (OFF_PAR + 3072)          // 95232
#define GSMEM   (OFF_RED + 2048)          // 97280

__global__ void __launch_bounds__(256, 2) k_gemmfused(int layer,
                       const float* __restrict__ bias,
                       const float* __restrict__ gm, const float* __restrict__ bt){
  extern __shared__ char smem[];
  uint32_t sbase = smem_u32(smem);
  float* s_bias = (float*)(smem + OFF_PAR);
  float* s_g    = (float*)(smem + OFF_PAR + 1024);
  float* s_bt   = (float*)(smem + OFF_PAR + 2048);
  float* s_red  = (float*)(smem + OFF_RED);

  int tid = threadIdx.x, lane = tid & 31, wid = tid >> 5;
  int warpM = wid >> 2, warpN = wid & 3;
  int g = lane >> 2, tig = lane & 3;
  int mat = lane >> 3, mr = lane & 7;
  int n0 = blockIdx.x * 64;

  const char* wt = (const char*)(g_wt + (size_t)layer*HCH*HCH);
  const char* ya = (const char*)g_y;

  s_bias[tid] = bias[tid]; s_g[tid] = gm[tid]; s_bt[tid] = bt[tid];

  float acc[2][8][4];
  #pragma unroll
  for (int mf=0;mf<2;mf++)
    #pragma unroll
    for (int nf=0;nf<8;nf++)
      #pragma unroll
      for (int k=0;k<4;k++) acc[mf][nf][k]=0.f;

  int arow = tid >> 2;            // 0..63
  int aq   = (tid & 3) * 32;      // byte offset within 128B segment
  uint32_t sa_st = sbase + OFF_A + arow*RSTR + aq;
  uint32_t sb_st = sbase + OFF_B + arow*RSTR + aq;
  const char* gA = ya + (size_t)(n0 + arow)*1024 + aq;

  // ldmatrix per-thread address components
  uint32_t aoff = (uint32_t)(((mat&1)*8 + mr)*RSTR + (mat>>1)*16);
  uint32_t boff = (uint32_t)(((mat>>1)*8 + mr)*RSTR + (mat&1)*16);

  #define ISSUE(q) {                                                       \
    int _kc = (q)*128;                                                     \
    int _bo = ((q)&1);                                                     \
    cp16(sa_st + _bo*A_BUF,      gA + _kc);                                \
    cp16(sa_st + _bo*A_BUF + 16, gA + _kc + 16);                           \
    _Pragma("unroll")                                                      \
    for (int _j=0;_j<4;_j++){                                              \
      const char* _s = wt + (size_t)(arow + 64*_j)*1024 + _kc + aq;        \
      uint32_t _d = sb_st + _bo*B_BUF + (64*_j)*RSTR;                      \
      cp16(_d, _s); cp16(_d + 16, _s + 16);                                \
    }                                                                      \
    CP_COMMIT();                                                           \
  }

  ISSUE(0);
  asm volatile("cp.async.wait_group 0;");
  __syncthreads();

  for (int q = 0; q < 8; q++){
    if (q + 1 < 8) ISSUE(q+1);

    int buf = q & 1;
    uint32_t aBase = sbase + OFF_A + buf*A_BUF + (warpM*32)*RSTR + aoff;
    uint32_t bBase = sbase + OFF_B + buf*B_BUF + (warpN*64)*RSTR + boff;

    #pragma unroll
    for (int ks=0; ks<4; ks++){
      int kb = ks*32;           // 8 floats per k-step
      unsigned afr[2][4];
      ldsm4(afr[0][0], afr[0][1], afr[0][2], afr[0][3], aBase + kb);
      ldsm4(afr[1][0], afr[1][1], afr[1][2], afr[1][3], aBase + 16*RSTR + kb);
      unsigned bfr[8][2];
      #pragma unroll
      for (int np=0; np<4; np++){
        unsigned t0,t1,t2,t3;
        ldsm4(t0,t1,t2,t3, bBase + np*16*RSTR + kb);
        bfr[2*np][0]=t0; bfr[2*np][1]=t1; bfr[2*np+1][0]=t2; bfr[2*np+1][1]=t3;
      }
      #pragma unroll
      for (int nf=0; nf<8; nf++){
        mma_tf32(acc[0][nf], afr[0], bfr[nf][0], bfr[nf][1]);
        mma_tf32(acc[1][nf], afr[1], bfr[nf][0], bfr[nf][1]);
      }
    }
    if (q + 1 < 8){
      asm volatile("cp.async.wait_group 0;");
      __syncthreads();
    }
  }

  // ---- epilogue: bias, row stats, LN, GELU, residual ----
  float s[4]  = {0.f,0.f,0.f,0.f};
  float sq[4] = {0.f,0.f,0.f,0.f};
  #pragma unroll
  for (int mf=0; mf<2; mf++)
    #pragma unroll
    for (int nf=0; nf<8; nf++){
      int ch0 = warpN*64 + nf*8 + tig*2;
      float b0 = s_bias[ch0], b1 = s_bias[ch0+1];
      acc[mf][nf][0]+=b0; acc[mf][nf][1]+=b1;
      acc[mf][nf][2]+=b0; acc[mf][nf][3]+=b1;
      s [mf*2+0] += acc[mf][nf][0]+acc[mf][nf][1];
      sq[mf*2+0] += acc[mf][nf][0]*acc[mf][nf][0] + acc[mf][nf][1]*acc[mf][nf][1];
      s [mf*2+1] += acc[mf][nf][2]+acc[mf][nf][3];
      sq[mf*2+1] += acc[mf][nf][2]*acc[mf][nf][2] + acc[mf][nf][3]*acc[mf][nf][3];
    }
  #pragma unroll
  for (int sl=0; sl<4; sl++){
    s [sl] += __shfl_xor_sync(0xffffffffu, s [sl], 1);
    s [sl] += __shfl_xor_sync(0xffffffffu, s [sl], 2);
    sq[sl] += __shfl_xor_sync(0xffffffffu, sq[sl], 1);
    sq[sl] += __shfl_xor_sync(0xffffffffu, sq[sl], 2);
  }
  __syncthreads();
  if (tig == 0){
    #pragma unroll
    for (int sl=0; sl<4; sl++){
      int mf = sl >> 1, h = sl & 1;
      int row = warpM*32 + mf*16 + h*8 + g;
      s_red[row*8 + warpN*2 + 0] = s[sl];
      s_red[row*8 + warpN*2 + 1] = sq[sl];
    }
  }
  __syncthreads();

  float mean_[4], rstd_[4];
  #pragma unroll
  for (int sl=0; sl<4; sl++){
    int mf = sl >> 1, h = sl & 1;
    int row = warpM*32 + mf*16 + h*8 + g;
    float su = s_red[row*8+0]+s_red[row*8+2]+s_red[row*8+4]+s_red[row*8+6];
    float qq = s_red[row*8+1]+s_red[row*8+3]+s_red[row*8+5]+s_red[row*8+7];
    float mn = su * (1.f/HCH);
    float var = qq * (1.f/HCH) - mn*mn;
    mean_[sl] = mn;
    rstd_[sl] = rsqrtf(var + 1e-5f);
  }

  #pragma unroll
  for (int mf=0; mf<2; mf++)
    #pragma unroll
    for (int nf=0; nf<8; nf++){
      int ch0 = warpN*64 + nf*8 + tig*2;
      float g0 = s_g[ch0], g1 = s_g[ch0+1];
      float t0 = s_bt[ch0], t1 = s_bt[ch0+1];
      #pragma unroll
      for (int h=0; h<2; h++){
        int sl = mf*2 + h;
        int row = n0 + warpM*32 + mf*16 + h*8 + g;
        float v0 = (acc[mf][nf][h*2+0] - mean_[sl])*rstd_[sl]*g0 + t0;
        float v1 = (acc[mf][nf][h*2+1] - mean_[sl])*rstd_[sl]*g1 + t1;
        float2* ptr = (float2*)&g_h[(size_t)row*HCH + ch0];
        float2 hv = *ptr;
        hv.x += gelu_exact(v0);
        hv.y += gelu_exact(v1);
        *ptr = hv;
      }
    }
}

// ---------------- pad proj weights ----------------
__global__ void k_padw(const float* __restrict__ pjw, const float* __restrict__ pjb){
  int o = blockIdx.x, c = threadIdx.x;
  g_pw[o*HCH + c] = (o < OUTCH) ? pjw[o*HCH + c] : 0.f;
  if (c == 0) g_pb[o] = (o < OUTCH) ? pjb[o] : 0.f;
}

// ---------------- projection GEMM (fp32 SIMT; precision-critical path) ----------------
__global__ void __launch_bounds__(256) k_projgemm(const float* __restrict__ mask){
  __shared__ float sA[16][128];
  __shared__ float sB[16][64];
  int tid = threadIdx.x;
  int n0 = blockIdx.x*128;
  int tx = tid & 7, ty = tid >> 3;
  float acc[4][8];
  #pragma unroll
  for (int i=0;i<4;i++)
    #pragma unroll
    for (int j=0;j<8;j++) acc[i][j]=0.f;

  for (int c0=0;c0<HCH;c0+=16){
    #pragma unroll
    for (int u=0;u<2;u++){
      int f = tid + u*256;
      int row = f >> 2;
      int cc4 = (f & 3) << 2;
      float m = mask[n0+row];
      float4 av = *(const float4*)&g_h[(size_t)(n0+row)*HCH + c0 + cc4];
      sA[cc4+0][row]=av.x*m; sA[cc4+1][row]=av.y*m; sA[cc4+2][row]=av.z*m; sA[cc4+3][row]=av.w*m;
    }
    {
      int row = tid >> 2;
      int cc4 = (tid & 3) << 2;
      float4 wv = *(const float4*)&g_pw[row*HCH + c0 + cc4];
      sB[cc4+0][row]=wv.x; sB[cc4+1][row]=wv.y; sB[cc4+2][row]=wv.z; sB[cc4+3][row]=wv.w;
    }
    __syncthreads();
    #pragma unroll
    for (int cc=0; cc<16; cc++){
      float a[4], b[8];
      *(float4*)&a[0] = *(const float4*)&sA[cc][ty*4];
      *(float4*)&b[0] = *(const float4*)&sB[cc][tx*8];
      *(float4*)&b[4] = *(const float4*)&sB[cc][tx*8+4];
      #pragma unroll
      for (int i=0;i<4;i++)
        #pragma unroll
        for (int j=0;j<8;j++) acc[i][j] = fmaf(a[i], b[j], acc[i][j]);
    }
    __syncthreads();
  }
  #pragma unroll
  for (int i=0;i<4;i++){
    int n = n0 + ty*4 + i;
    float m = mask[n];
    #pragma unroll
    for (int j=0;j<8;j++){
      int o = tx*8 + j;
      g_p[(size_t)n*OPAD + o] = (acc[i][j] + g_pb[o]) * m;
    }
  }
}

// ---------------- rational-quadratic spline ----------------
__global__ void k_spline(const float* __restrict__ x, const float* __restrict__ mask,
                         float* __restrict__ out){
  int i = blockIdx.x*256 + threadIdx.x;
  int t = i & (TLEN-1);
  int bc = i >> 12;
  int c = bc & 1, b = bc >> 1;
  float m = mask[b*TLEN + t];
  const float* p = &g_p[(size_t)(b*TLEN + t)*OPAD + c*29];
  float x1 = x[(b*4 + 2 + c)*TLEN + t];

  out[(b*4 + c)*TLEN + t] = x[(b*4 + c)*TLEN + t] * m;

  const float scale = 0.0625f;
  float ew[10], eh[10];
  float mw = -1e30f, mh = -1e30f;
  #pragma unroll
  for (int j=0;j<10;j++){ mw = fmaxf(mw, p[j]*scale); mh = fmaxf(mh, p[10+j]*scale); }
  float sw = 0.f, sh = 0.f;
  #pragma unroll
  for (int j=0;j<10;j++){
    ew[j] = expf(p[j]*scale - mw);    sw += ew[j];
    eh[j] = expf(p[10+j]*scale - mh); sh += eh[j];
  }
  float invsw = 1.f/sw, invsh = 1.f/sh;
  float xc = fminf(fmaxf(x1, -5.f), 5.f);

  float cumw = 0.f, cumh = 0.f;
  float cwj = -5.f, chj = -5.f;
  int idx = 9;
  float in_cw = 0.f, in_w = 1.f, in_ch = 0.f, in_h = 1.f;
  bool found = false;
  #pragma unroll
  for (int j=0;j<10;j++){
    cumw += 0.001f + 0.99f*ew[j]*invsw;
    cumh += 0.001f + 0.99f*eh[j]*invsh;
    float nw = (j==9) ? 5.f : fmaf(10.f, cumw, -5.f);
    float nh = (j==9) ? 5.f : fmaf(10.f, cumh, -5.f);
    if (!found && (xc < nw || j==9)){
      found = true; idx = j;
      in_cw = cwj; in_w = nw - cwj;
      in_ch = chj; in_h = nh - chj;
    }
    cwj = nw; chj = nh;
  }
  float dk  = (idx==0) ? 1.f : 0.001f + softplusf(p[20 + idx - 1]);
  float dk1 = (idx==9) ? 1.f : 0.001f + softplusf(p[20 + idx]);
  float delta = in_h / in_w;
  float th  = (xc - in_cw) / in_w;
  float th2 = th*th;
  float t1m = th*(1.f - th);
  float num = in_h * (delta*th2 + dk*t1m);
  float den = delta + (dk + dk1 - 2.f*delta)*t1m;
  float y = in_ch + num/den;
  float omt = 1.f - th;
  float dnum = delta*delta*(dk1*th2 + 2.f*delta*t1m + dk*omt*omt);
  float lad = logf(dnum) - 2.f*logf(den);

  bool inside = (x1 >= -5.f) && (x1 <= 5.f);
  y   = inside ? y   : x1;
  lad = inside ? lad : 0.f;

  out[(b*4 + 2 + c)*TLEN + t] = y * m;
  g_lad[i] = lad * m;
}

__global__ void k_reduce(float* __restrict__ out){
  int b = blockIdx.x;
  float s = 0.f;
  for (int j = threadIdx.x; j < 2*TLEN; j += 256) s += g_lad[b*2*TLEN + j];
  __shared__ float sm[8];
  #pragma unroll
  for (int o=16;o;o>>=1) s += __shfl_xor_sync(0xffffffffu, s, o);
  if ((threadIdx.x&31)==0) sm[threadIdx.x>>5]=s;
  __syncthreads();
  if (threadIdx.x == 0){
    float r = sm[0]+sm[1]+sm[2]+sm[3]+sm[4]+sm[5]+sm[6]+sm[7];
    out[BATCH*4*TLEN + b] = r;
  }
}

extern "C" void kernel_launch(void* const* d_in, const int* in_sizes, int n_in,
                              void* d_out, int out_size){
  const float* x     = (const float*)d_in[0];
  const float* xm    = (const float*)d_in[1];
  const float* pre_w = (const float*)d_in[2];
  const float* pre_b = (const float*)d_in[3];
  const float* sep_w = (const float*)d_in[4];
  const float* sep_b = (const float*)d_in[5];
  const float* c1w   = (const float*)d_in[6];
  const float* c1b   = (const float*)d_in[7];
  const float* n1g   = (const float*)d_in[8];
  const float* n1b   = (const float*)d_in[9];
  const float* n2g   = (const float*)d_in[10];
  const float* n2b   = (const float*)d_in[11];
  const float* pjw   = (const float*)d_in[12];
  const float* pjb   = (const float*)d_in[13];
  float* out = (float*)d_out;

  static int smem_set = 0;
  if (!smem_set){
    cudaFuncSetAttribute(k_gemmfused, cudaFuncAttributeMaxDynamicSharedMemorySize, GSMEM);
    smem_set = 1;
  }

  k_pre<<<(NPOS*HCH)/256, 256>>>(x, pre_w, pre_b);
  k_wprep<<<(LLAYER*HCH*HCH)/256, 256>>>(c1w);

  int dil = 1;
  for (int i=0;i<LLAYER;i++){
    k_dwln<<<NPOS/8, 256>>>(xm, sep_w + i*HCH*3, sep_b + i*HCH,
                            n1g + i*HCH, n1b + i*HCH, dil);
    k_gemmfused<<<NPOS/64, 256, GSMEM>>>(i, c1b + i*HCH, n2g + i*HCH, n2b + i*HCH);
    dil *= 3;
  }

  k_padw<<<OPAD, HCH>>>(pjw, pjb);
  k_projgemm<<<NPOS/128, 256>>>(xm);
  k_spline<<<(BATCH*2*TLEN)/256, 256>>>(x, xm, out);
  k_reduce<<<BATCH, 256>>>(out);
}